// round 1
// baseline (speedup 1.0000x reference)
#include <cuda_runtime.h>
#include <math.h>

#define BB   8
#define CIN  16
#define HID  128
#define HW   64
#define NPIX (HW*HW)          // 4096
#define NTOK (BB*NPIX)        // 32768
#define KC   8192             // codebook size

// scratch (device globals: no allocation allowed)
__device__ float g_h1[BB*HID*NPIX];    // 16 MB: h1, later q
__device__ float g_h2[BB*HID*NPIX];    // 16 MB: h2, later y
__device__ float g_embT[HID*KC];       // 4 MB transposed codebook
__device__ float g_enorm[KC];
__device__ int   g_idx[NTOK];

__device__ __forceinline__ float gelu_exact(float x) {
    return 0.5f * x * (1.0f + erff(x * 0.70710678118654752440f));
}

// ---------------------------------------------------------------- transpose embed -> [D][K]
__global__ void transpose_embed_kernel(const float* __restrict__ e) {
    __shared__ float s[32][33];
    int k0 = blockIdx.x * 32, d0 = blockIdx.y * 32;
    int tx = threadIdx.x, ty = threadIdx.y;            // (32,8)
    #pragma unroll
    for (int j = 0; j < 4; j++)
        s[ty + 8*j][tx] = e[(k0 + ty + 8*j) * HID + d0 + tx];
    __syncthreads();
    #pragma unroll
    for (int j = 0; j < 4; j++)
        g_embT[(size_t)(d0 + ty + 8*j) * KC + k0 + tx] = s[tx][ty + 8*j];
}

// ---------------------------------------------------------------- ||e||^2 per code
__global__ void enorm_kernel(const float* __restrict__ e) {
    int warp = (blockIdx.x * blockDim.x + threadIdx.x) >> 5;
    int lane = threadIdx.x & 31;
    if (warp >= KC) return;
    float4 v = *(const float4*)(e + (size_t)warp * HID + lane * 4);
    float s = v.x*v.x + v.y*v.y + v.z*v.z + v.w*v.w;
    #pragma unroll
    for (int o = 16; o; o >>= 1) s += __shfl_xor_sync(0xffffffffu, s, o);
    if (lane == 0) g_enorm[warp] = s;
}

// ---------------------------------------------------------------- conv1: 16 -> 128, 3x3 SAME, GELU
__global__ void conv1_kernel(const float* __restrict__ x, const float* __restrict__ w,
                             const float* __restrict__ bias) {
    __shared__ float in_s[CIN * 324];      // 16 x 18 x 18
    __shared__ float w_s[32 * CIN * 9];
    int tile = blockIdx.x, ocb = blockIdx.y, b = blockIdx.z;
    int ty0 = (tile >> 2) * 16, tx0 = (tile & 3) * 16;
    int tid = threadIdx.x;

    for (int e = tid; e < 32 * CIN * 9; e += 256)
        w_s[e] = w[ocb * 32 * CIN * 9 + e];

    const float* xb = x + (size_t)b * CIN * NPIX;
    for (int e = tid; e < CIN * 324; e += 256) {
        int ci = e / 324, r = e % 324;
        int iy = r / 18, ix = r % 18;
        int gy = ty0 + iy - 1, gx = tx0 + ix - 1;
        float v = 0.f;
        if ((unsigned)gy < 64u && (unsigned)gx < 64u)
            v = xb[ci * NPIX + gy * HW + gx];
        in_s[e] = v;
    }
    __syncthreads();

    int px = tid & 15, py = tid >> 4;
    float acc[32];
    #pragma unroll
    for (int o = 0; o < 32; o++) acc[o] = 0.f;

    #pragma unroll 2
    for (int ci = 0; ci < CIN; ci++) {
        #pragma unroll
        for (int kk = 0; kk < 9; kk++) {
            int ky = kk / 3, kx = kk % 3;
            float v = in_s[ci * 324 + (py + ky) * 18 + (px + kx)];
            #pragma unroll
            for (int o = 0; o < 32; o++)
                acc[o] += w_s[o * (CIN * 9) + ci * 9 + kk] * v;
        }
    }

    int gy = ty0 + py, gx = tx0 + px;
    #pragma unroll
    for (int o = 0; o < 32; o++) {
        int oc = ocb * 32 + o;
        g_h1[((size_t)(b * HID + oc)) * NPIX + gy * HW + gx] = gelu_exact(acc[o] + bias[oc]);
    }
}

// ---------------------------------------------------------------- conv 128 -> 128, 3x3 SAME, GELU
__global__ void conv_hid_kernel(const float* __restrict__ in, const float* __restrict__ w,
                                const float* __restrict__ bias, float* __restrict__ out) {
    __shared__ float in_s[16 * 324];
    __shared__ float w_s[32 * 16 * 9];
    int tile = blockIdx.x, ocb = blockIdx.y, b = blockIdx.z;
    int ty0 = (tile >> 2) * 16, tx0 = (tile & 3) * 16;
    int tid = threadIdx.x;
    int px = tid & 15, py = tid >> 4;

    float acc[32];
    #pragma unroll
    for (int o = 0; o < 32; o++) acc[o] = 0.f;

    for (int cc = 0; cc < HID / 16; cc++) {
        int ci0 = cc * 16;
        __syncthreads();
        for (int e = tid; e < 16 * 324; e += 256) {
            int ci = e / 324, r = e % 324;
            int iy = r / 18, ix = r % 18;
            int gy = ty0 + iy - 1, gx = tx0 + ix - 1;
            float v = 0.f;
            if ((unsigned)gy < 64u && (unsigned)gx < 64u)
                v = in[((size_t)(b * HID + ci0 + ci)) * NPIX + gy * HW + gx];
            in_s[e] = v;
        }
        for (int e = tid; e < 32 * 144; e += 256) {
            int o = e / 144, r = e % 144;
            w_s[e] = w[(size_t)(ocb * 32 + o) * (HID * 9) + ci0 * 9 + r];
        }
        __syncthreads();

        #pragma unroll 2
        for (int ci = 0; ci < 16; ci++) {
            #pragma unroll
            for (int kk = 0; kk < 9; kk++) {
                int ky = kk / 3, kx = kk % 3;
                float v = in_s[ci * 324 + (py + ky) * 18 + (px + kx)];
                #pragma unroll
                for (int o = 0; o < 32; o++)
                    acc[o] += w_s[o * 144 + ci * 9 + kk] * v;
            }
        }
    }

    int gy = ty0 + py, gx = tx0 + px;
    #pragma unroll
    for (int o = 0; o < 32; o++) {
        int oc = ocb * 32 + o;
        out[((size_t)(b * HID + oc)) * NPIX + gy * HW + gx] = gelu_exact(acc[o] + bias[oc]);
    }
}

// ---------------------------------------------------------------- VQ: fused distance GEMM + argmin
// block: 64 tokens x all 8192 codes; threads 256 (16x16), 4x4 register tile.
__global__ void vq_argmin_kernel() {
    extern __shared__ float sm[];
    float* Fs  = sm;                 // [128][64] token features, d-major
    float* Es  = sm + 128 * 64;      // [128][64] code features, d-major
    float* Ens = sm + 2 * 128 * 64;  // [64] code sq-norms

    int n0 = blockIdx.x * 64;        // 64 consecutive tokens (one image row)
    int b  = n0 / NPIX;
    int hw0 = n0 % NPIX;
    const float* fb = g_h2 + (size_t)b * HID * NPIX + hw0;
    int tid = threadIdx.x;

    #pragma unroll
    for (int it = 0; it < 32; it++) {       // 128*64 elems
        int e = it * 256 + tid;
        int d = e >> 6, t = e & 63;
        Fs[e] = fb[d * NPIX + t];
    }

    int tx = tid & 15, ty = tid >> 4;
    unsigned long long best[4] = {~0ull, ~0ull, ~0ull, ~0ull};

    for (int ct = 0; ct < KC / 64; ct++) {
        int c0 = ct * 64;
        __syncthreads();
        #pragma unroll
        for (int it = 0; it < 32; it++) {
            int e = it * 256 + tid;
            int d = e >> 6, t = e & 63;
            Es[e] = g_embT[(size_t)d * KC + c0 + t];
        }
        if (tid < 64) Ens[tid] = g_enorm[c0 + tid];
        __syncthreads();

        float acc[4][4];
        #pragma unroll
        for (int i = 0; i < 4; i++)
            #pragma unroll
            for (int j = 0; j < 4; j++) acc[i][j] = 0.f;

        #pragma unroll 8
        for (int k = 0; k < 128; k++) {
            float4 a = *(const float4*)(Fs + k * 64 + ty * 4);
            float4 c = *(const float4*)(Es + k * 64 + tx * 4);
            acc[0][0] += a.x * c.x; acc[0][1] += a.x * c.y; acc[0][2] += a.x * c.z; acc[0][3] += a.x * c.w;
            acc[1][0] += a.y * c.x; acc[1][1] += a.y * c.y; acc[1][2] += a.y * c.z; acc[1][3] += a.y * c.w;
            acc[2][0] += a.z * c.x; acc[2][1] += a.z * c.y; acc[2][2] += a.z * c.z; acc[2][3] += a.z * c.w;
            acc[3][0] += a.w * c.x; acc[3][1] += a.w * c.y; acc[3][2] += a.w * c.z; acc[3][3] += a.w * c.w;
        }

        #pragma unroll
        for (int j = 0; j < 4; j++) {
            float en = Ens[tx * 4 + j];
            unsigned cidx = (unsigned)(c0 + tx * 4 + j);
            #pragma unroll
            for (int i = 0; i < 4; i++) {
                float s = en - 2.0f * acc[i][j];
                unsigned u = __float_as_uint(s);
                u = (u & 0x80000000u) ? ~u : (u | 0x80000000u);  // order-monotonic
                unsigned long long key = ((unsigned long long)u << 32) | cidx;
                if (key < best[i]) best[i] = key;
            }
        }
    }

    // reduce across the 16 tx threads (half-warp) per token
    #pragma unroll
    for (int i = 0; i < 4; i++) {
        unsigned long long k = best[i];
        #pragma unroll
        for (int off = 8; off; off >>= 1) {
            unsigned long long o = __shfl_xor_sync(0xffffffffu, k, off, 16);
            if (o < k) k = o;
        }
        if (tx == 0) g_idx[n0 + ty * 4 + i] = (int)(k & 0xFFFFFFFFu);
    }
}

// ---------------------------------------------------------------- gather codebook -> NCHW q
__global__ void gather_kernel(const float* __restrict__ embed) {
    int n = blockIdx.x * 256 + threadIdx.x;  // 0..32767
    int id = g_idx[n];
    int b = n / NPIX, hw = n % NPIX;
    float* q = g_h1 + (size_t)b * HID * NPIX + hw;
    const float* er = embed + (size_t)id * HID;
    #pragma unroll 4
    for (int d = 0; d < HID; d += 4) {
        float4 v = *(const float4*)(er + d);
        q[(d + 0) * NPIX] = v.x;
        q[(d + 1) * NPIX] = v.y;
        q[(d + 2) * NPIX] = v.z;
        q[(d + 3) * NPIX] = v.w;
    }
}

// ---------------------------------------------------------------- conv1x1 128->16 + sigmoid
__global__ void conv1x1_sigmoid_kernel(const float* __restrict__ y, const float* __restrict__ w,
                                       const float* __restrict__ bias, float* __restrict__ out) {
    __shared__ float w_s[CIN * HID];
    int tid = threadIdx.x;
    for (int e = tid; e < CIN * HID; e += 256) w_s[e] = w[e];
    __syncthreads();

    int b = blockIdx.y;
    int p = blockIdx.x * 256 + tid;
    const float* yb = y + (size_t)b * HID * NPIX + p;
    float acc[CIN];
    #pragma unroll
    for (int c = 0; c < CIN; c++) acc[c] = 0.f;
    #pragma unroll 4
    for (int d = 0; d < HID; d++) {
        float v = yb[d * NPIX];
        #pragma unroll
        for (int c = 0; c < CIN; c++) acc[c] += w_s[c * HID + d] * v;
    }
    #pragma unroll
    for (int c = 0; c < CIN; c++) {
        float s = acc[c] + bias[c];
        out[((size_t)(b * CIN + c)) * NPIX + p] = 1.0f / (1.0f + expf(-s));
    }
}

// ----------------------------------------------------------------
extern "C" void kernel_launch(void* const* d_in, const int* in_sizes, int n_in,
                              void* d_out, int out_size) {
    const float* x     = (const float*)d_in[0];
    const float* ew1   = (const float*)d_in[1];
    const float* eb1   = (const float*)d_in[2];
    const float* ew2   = (const float*)d_in[3];
    const float* eb2   = (const float*)d_in[4];
    const float* embed = (const float*)d_in[5];
    const float* dw1   = (const float*)d_in[6];
    const float* db1   = (const float*)d_in[7];
    const float* dw2   = (const float*)d_in[8];
    const float* db2   = (const float*)d_in[9];
    float* out = (float*)d_out;

    float *p_h1, *p_h2;
    cudaGetSymbolAddress((void**)&p_h1, g_h1);
    cudaGetSymbolAddress((void**)&p_h2, g_h2);

    const int VQ_SMEM = (2 * 128 * 64 + 64) * sizeof(float);  // 65792 B
    cudaFuncSetAttribute(vq_argmin_kernel, cudaFuncAttributeMaxDynamicSharedMemorySize, VQ_SMEM);

    // codebook prep
    transpose_embed_kernel<<<dim3(KC / 32, HID / 32), dim3(32, 8)>>>(embed);
    enorm_kernel<<<KC * 32 / 256, 256>>>(embed);

    // encoder
    conv1_kernel<<<dim3(16, 4, BB), 256>>>(x, ew1, eb1);
    conv_hid_kernel<<<dim3(16, 4, BB), 256>>>(p_h1, ew2, eb2, p_h2);

    // VQ
    vq_argmin_kernel<<<NTOK / 64, 256, VQ_SMEM>>>();
    gather_kernel<<<NTOK / 256, 256>>>(embed);

    // decoder
    conv_hid_kernel<<<dim3(16, 4, BB), 256>>>(p_h1, dw1, db1, p_h2);
    conv1x1_sigmoid_kernel<<<dim3(NPIX / 256, BB), 256>>>(p_h2, dw2, db2, out);
}

// round 2
// speedup vs baseline: 1.2209x; 1.2209x over previous
#include <cuda_runtime.h>
#include <math.h>

#define BB   8
#define CIN  16
#define HID  128
#define HW   64
#define NPIX (HW*HW)          // 4096
#define NTOK (BB*NPIX)        // 32768
#define KC   8192             // codebook size

typedef unsigned long long ull;

// scratch (device globals: no allocation allowed)
__device__ float g_h1[BB*HID*NPIX];    // 16 MB: h1, later q
__device__ float g_h2[BB*HID*NPIX];    // 16 MB: h2, later y
__device__ float g_embT[HID*KC];       // 4 MB transposed codebook
__device__ float g_enorm[KC];
__device__ int   g_idx[NTOK];
__device__ float g_wT_e1[CIN*9*HID];   // transposed conv weights [ci*9+kk][oc]
__device__ float g_wT_e2[HID*9*HID];
__device__ float g_wT_d1[HID*9*HID];

__device__ __forceinline__ float gelu_exact(float x) {
    return 0.5f * x * (1.0f + erff(x * 0.70710678118654752440f));
}

__device__ __forceinline__ ull pack2(float x, float y) {
    ull r; asm("mov.b64 %0, {%1, %2};" : "=l"(r) : "f"(x), "f"(y)); return r;
}
__device__ __forceinline__ void unpack2(ull v, float& x, float& y) {
    asm("mov.b64 {%0, %1}, %2;" : "=f"(x), "=f"(y) : "l"(v));
}
__device__ __forceinline__ ull ffma2(ull a, ull b, ull c) {
    ull d; asm("fma.rn.f32x2 %0, %1, %2, %3;" : "=l"(d) : "l"(a), "l"(b), "l"(c)); return d;
}

// ---------------------------------------------------------------- transpose embed -> [D][K]
__global__ void transpose_embed_kernel(const float* __restrict__ e) {
    __shared__ float s[32][33];
    int k0 = blockIdx.x * 32, d0 = blockIdx.y * 32;
    int tx = threadIdx.x, ty = threadIdx.y;            // (32,8)
    #pragma unroll
    for (int j = 0; j < 4; j++)
        s[ty + 8*j][tx] = e[(k0 + ty + 8*j) * HID + d0 + tx];
    __syncthreads();
    #pragma unroll
    for (int j = 0; j < 4; j++)
        g_embT[(size_t)(d0 + ty + 8*j) * KC + k0 + tx] = s[tx][ty + 8*j];
}

// ---------------------------------------------------------------- ||e||^2 per code
__global__ void enorm_kernel(const float* __restrict__ e) {
    int warp = (blockIdx.x * blockDim.x + threadIdx.x) >> 5;
    int lane = threadIdx.x & 31;
    if (warp >= KC) return;
    float4 v = *(const float4*)(e + (size_t)warp * HID + lane * 4);
    float s = v.x*v.x + v.y*v.y + v.z*v.z + v.w*v.w;
    #pragma unroll
    for (int o = 16; o; o >>= 1) s += __shfl_xor_sync(0xffffffffu, s, o);
    if (lane == 0) g_enorm[warp] = s;
}

// ---------------------------------------------------------------- transpose conv weight [oc][ci*9] -> [ci*9][oc]
__global__ void transpose_w_kernel(const float* __restrict__ w, float* __restrict__ wT, int cin) {
    int e = blockIdx.x * 256 + threadIdx.x;
    int total = cin * 9 * HID;
    if (e >= total) return;
    int row = e >> 7, oc = e & 127;     // row = ci*9+kk
    wT[e] = w[(size_t)oc * cin * 9 + row];
}

// ---------------------------------------------------------------- conv 3x3 SAME + GELU (f32x2)
// in: [B][cin][64][64], wT: [(ci*9+kk)][128], out: [B][128][64][64]
__global__ void conv3x3_f2_kernel(const float* __restrict__ in, const float* __restrict__ wT,
                                  const float* __restrict__ bias, float* __restrict__ out, int cin) {
    __shared__ float in_s[16 * 324];          // 16 ci x 18 x 18
    __shared__ float w_s[144 * 32];           // [ci*9+kk][32 oc]
    int tile = blockIdx.x, ocb = blockIdx.y, b = blockIdx.z;
    int ty0 = (tile >> 2) * 16, tx0 = (tile & 3) * 16;
    int tid = threadIdx.x;
    int px = tid & 15, py = tid >> 4;

    ull acc[16];
    #pragma unroll
    for (int o = 0; o < 16; o++) acc[o] = 0ull;

    int chunks = cin >> 4;
    for (int cc = 0; cc < chunks; cc++) {
        int ci0 = cc * 16;
        __syncthreads();
        for (int e = tid; e < 16 * 324; e += 256) {
            int ci = e / 324, r = e % 324;
            int iy = r / 18, ix = r % 18;
            int gy = ty0 + iy - 1, gx = tx0 + ix - 1;
            float v = 0.f;
            if ((unsigned)gy < 64u && (unsigned)gx < 64u)
                v = in[((size_t)b * cin + ci0 + ci) * NPIX + gy * HW + gx];
            in_s[e] = v;
        }
        for (int e = tid; e < 144 * 32; e += 256) {
            int r = e >> 5, o = e & 31;
            w_s[e] = wT[(size_t)(ci0 * 9 + r) * HID + ocb * 32 + o];
        }
        __syncthreads();

        for (int ci = 0; ci < 16; ci++) {
            #pragma unroll
            for (int ky = 0; ky < 3; ky++) {
                #pragma unroll
                for (int kx = 0; kx < 3; kx++) {
                    float v = in_s[ci * 324 + (py + ky) * 18 + (px + kx)];
                    ull vd = pack2(v, v);
                    const ulonglong2* wp = (const ulonglong2*)(w_s + (ci * 9 + ky * 3 + kx) * 32);
                    #pragma unroll
                    for (int q = 0; q < 8; q++) {
                        ulonglong2 wv = wp[q];
                        acc[2*q]   = ffma2(wv.x, vd, acc[2*q]);
                        acc[2*q+1] = ffma2(wv.y, vd, acc[2*q+1]);
                    }
                }
            }
        }
    }

    int gy = ty0 + py, gx = tx0 + px;
    #pragma unroll
    for (int o = 0; o < 16; o++) {
        float f0, f1;
        unpack2(acc[o], f0, f1);
        int oc = ocb * 32 + 2 * o;
        out[((size_t)(b * HID + oc)) * NPIX + gy * HW + gx]     = gelu_exact(f0 + bias[oc]);
        out[((size_t)(b * HID + oc + 1)) * NPIX + gy * HW + gx] = gelu_exact(f1 + bias[oc + 1]);
    }
}

// ---------------------------------------------------------------- VQ: fused distance GEMM + argmin (f32x2)
// block: 128 tokens x 64-code tiles over all 8192 codes; 256 threads, 8x4 per thread.
__global__ void vq_argmin_kernel() {
    extern __shared__ float sm[];
    float* Fs  = sm;                      // [128 d][128 tok]
    float* Es  = sm + 128 * 128;          // [128 d][64 code]
    float* Ens = sm + 128 * 128 + 128 * 64;

    int tid = threadIdx.x;
    int n0 = blockIdx.x * 128;
    int b  = n0 / NPIX;
    int hw0 = n0 % NPIX;
    const float* fb = g_h2 + (size_t)b * HID * NPIX + hw0;

    #pragma unroll
    for (int it = 0; it < 16; it++) {     // 4096 float4
        int e = it * 256 + tid;
        int d = e >> 5, t4 = e & 31;
        ((float4*)Fs)[e] = *(const float4*)(fb + d * NPIX + t4 * 4);
    }

    int tx = tid & 15, ty = tid >> 4;     // tx: 4 codes each (64), ty: 8 tokens each (128)
    ull best[8];
    #pragma unroll
    for (int i = 0; i < 8; i++) best[i] = ~0ull;

    for (int ct = 0; ct < KC / 64; ct++) {
        int c0 = ct * 64;
        __syncthreads();
        #pragma unroll
        for (int it = 0; it < 8; it++) {  // 2048 float4
            int e = it * 256 + tid;
            int d = e >> 4, t4 = e & 15;
            ((float4*)Es)[e] = *(const float4*)(g_embT + (size_t)d * KC + c0 + t4 * 4);
        }
        if (tid < 64) Ens[tid] = g_enorm[c0 + tid];
        __syncthreads();

        ull acc[4][4];
        #pragma unroll
        for (int i = 0; i < 4; i++)
            #pragma unroll
            for (int j = 0; j < 4; j++) acc[i][j] = 0ull;

        #pragma unroll 4
        for (int k = 0; k < 128; k++) {
            const ulonglong2* ap = (const ulonglong2*)(Fs + k * 128 + ty * 8);
            ulonglong2 A0 = ap[0], A1 = ap[1];          // token pairs (0,1)(2,3)(4,5)(6,7)
            float4 C = *(const float4*)(Es + k * 64 + tx * 4);
            ull c0d = pack2(C.x, C.x), c1d = pack2(C.y, C.y);
            ull c2d = pack2(C.z, C.z), c3d = pack2(C.w, C.w);
            acc[0][0] = ffma2(A0.x, c0d, acc[0][0]); acc[0][1] = ffma2(A0.x, c1d, acc[0][1]);
            acc[0][2] = ffma2(A0.x, c2d, acc[0][2]); acc[0][3] = ffma2(A0.x, c3d, acc[0][3]);
            acc[1][0] = ffma2(A0.y, c0d, acc[1][0]); acc[1][1] = ffma2(A0.y, c1d, acc[1][1]);
            acc[1][2] = ffma2(A0.y, c2d, acc[1][2]); acc[1][3] = ffma2(A0.y, c3d, acc[1][3]);
            acc[2][0] = ffma2(A1.x, c0d, acc[2][0]); acc[2][1] = ffma2(A1.x, c1d, acc[2][1]);
            acc[2][2] = ffma2(A1.x, c2d, acc[2][2]); acc[2][3] = ffma2(A1.x, c3d, acc[2][3]);
            acc[3][0] = ffma2(A1.y, c0d, acc[3][0]); acc[3][1] = ffma2(A1.y, c1d, acc[3][1]);
            acc[3][2] = ffma2(A1.y, c2d, acc[3][2]); acc[3][3] = ffma2(A1.y, c3d, acc[3][3]);
        }

        #pragma unroll
        for (int j = 0; j < 4; j++) {
            float en = Ens[tx * 4 + j];
            unsigned cidx = (unsigned)(c0 + tx * 4 + j);
            #pragma unroll
            for (int ip = 0; ip < 4; ip++) {
                float s0, s1;
                unpack2(acc[ip][j], s0, s1);
                float d0 = en - 2.0f * s0;
                float d1 = en - 2.0f * s1;
                unsigned u0 = __float_as_uint(d0);
                u0 = (u0 & 0x80000000u) ? ~u0 : (u0 | 0x80000000u);
                unsigned u1 = __float_as_uint(d1);
                u1 = (u1 & 0x80000000u) ? ~u1 : (u1 | 0x80000000u);
                ull k0 = ((ull)u0 << 32) | cidx;
                ull k1 = ((ull)u1 << 32) | cidx;
                if (k0 < best[2*ip])   best[2*ip]   = k0;
                if (k1 < best[2*ip+1]) best[2*ip+1] = k1;
            }
        }
    }

    // reduce across the 16 tx threads (half-warp) per token
    #pragma unroll
    for (int i = 0; i < 8; i++) {
        ull k = best[i];
        #pragma unroll
        for (int off = 8; off; off >>= 1) {
            ull o = __shfl_xor_sync(0xffffffffu, k, off, 16);
            if (o < k) k = o;
        }
        if (tx == 0) g_idx[n0 + ty * 8 + i] = (int)(k & 0xFFFFFFFFu);
    }
}

// ---------------------------------------------------------------- gather codebook -> NCHW q
__global__ void gather_kernel(const float* __restrict__ embed) {
    int n = blockIdx.x * 256 + threadIdx.x;  // 0..32767
    int id = g_idx[n];
    int b = n / NPIX, hw = n % NPIX;
    float* q = g_h1 + (size_t)b * HID * NPIX + hw;
    const float* er = embed + (size_t)id * HID;
    #pragma unroll 4
    for (int d = 0; d < HID; d += 4) {
        float4 v = *(const float4*)(er + d);
        q[(d + 0) * NPIX] = v.x;
        q[(d + 1) * NPIX] = v.y;
        q[(d + 2) * NPIX] = v.z;
        q[(d + 3) * NPIX] = v.w;
    }
}

// ---------------------------------------------------------------- conv1x1 128->16 + sigmoid
__global__ void conv1x1_sigmoid_kernel(const float* __restrict__ y, const float* __restrict__ w,
                                       const float* __restrict__ bias, float* __restrict__ out) {
    __shared__ float w_s[CIN * HID];
    int tid = threadIdx.x;
    for (int e = tid; e < CIN * HID; e += 256) w_s[e] = w[e];
    __syncthreads();

    int b = blockIdx.y;
    int p = blockIdx.x * 256 + tid;
    const float* yb = y + (size_t)b * HID * NPIX + p;
    float acc[CIN];
    #pragma unroll
    for (int c = 0; c < CIN; c++) acc[c] = 0.f;
    #pragma unroll 4
    for (int d = 0; d < HID; d++) {
        float v = yb[d * NPIX];
        #pragma unroll
        for (int c = 0; c < CIN; c++) acc[c] += w_s[c * HID + d] * v;
    }
    #pragma unroll
    for (int c = 0; c < CIN; c++) {
        float s = acc[c] + bias[c];
        out[((size_t)(b * CIN + c)) * NPIX + p] = 1.0f / (1.0f + expf(-s));
    }
}

// ----------------------------------------------------------------
extern "C" void kernel_launch(void* const* d_in, const int* in_sizes, int n_in,
                              void* d_out, int out_size) {
    const float* x     = (const float*)d_in[0];
    const float* ew1   = (const float*)d_in[1];
    const float* eb1   = (const float*)d_in[2];
    const float* ew2   = (const float*)d_in[3];
    const float* eb2   = (const float*)d_in[4];
    const float* embed = (const float*)d_in[5];
    const float* dw1   = (const float*)d_in[6];
    const float* db1   = (const float*)d_in[7];
    const float* dw2   = (const float*)d_in[8];
    const float* db2   = (const float*)d_in[9];
    float* out = (float*)d_out;

    float *p_h1, *p_h2, *p_wT_e1, *p_wT_e2, *p_wT_d1;
    cudaGetSymbolAddress((void**)&p_h1, g_h1);
    cudaGetSymbolAddress((void**)&p_h2, g_h2);
    cudaGetSymbolAddress((void**)&p_wT_e1, g_wT_e1);
    cudaGetSymbolAddress((void**)&p_wT_e2, g_wT_e2);
    cudaGetSymbolAddress((void**)&p_wT_d1, g_wT_d1);

    const int VQ_SMEM = (128 * 128 + 128 * 64 + 64) * sizeof(float);  // 98560 B
    cudaFuncSetAttribute(vq_argmin_kernel, cudaFuncAttributeMaxDynamicSharedMemorySize, VQ_SMEM);

    // one-off prep: codebook transpose/norms + weight transposes
    transpose_embed_kernel<<<dim3(KC / 32, HID / 32), dim3(32, 8)>>>(embed);
    enorm_kernel<<<KC * 32 / 256, 256>>>(embed);
    transpose_w_kernel<<<(CIN * 9 * HID + 255) / 256, 256>>>(ew1, p_wT_e1, CIN);
    transpose_w_kernel<<<(HID * 9 * HID + 255) / 256, 256>>>(ew2, p_wT_e2, HID);
    transpose_w_kernel<<<(HID * 9 * HID + 255) / 256, 256>>>(dw1, p_wT_d1, HID);

    // encoder
    conv3x3_f2_kernel<<<dim3(16, 4, BB), 256>>>(x, p_wT_e1, eb1, p_h1, CIN);
    conv3x3_f2_kernel<<<dim3(16, 4, BB), 256>>>(p_h1, p_wT_e2, eb2, p_h2, HID);

    // VQ
    vq_argmin_kernel<<<NTOK / 128, 256, VQ_SMEM>>>();
    gather_kernel<<<NTOK / 256, 256>>>(embed);

    // decoder
    conv3x3_f2_kernel<<<dim3(16, 4, BB), 256>>>(p_h1, p_wT_d1, db1, p_h2, HID);
    conv1x1_sigmoid_kernel<<<dim3(NPIX / 256, BB), 256>>>(p_h2, dw2, db2, out);
}

// round 9
// speedup vs baseline: 2.1655x; 1.7737x over previous
#include <cuda_runtime.h>
#include <cuda_bf16.h>
#include <math.h>
#include <stdint.h>

#define BB   8
#define CIN  16
#define HID  128
#define HW   64
#define NPIX (HW*HW)          // 4096
#define NTOK (BB*NPIX)        // 32768
#define KC   8192             // codebook size
#define STILES 256            // 32-code supertiles

typedef unsigned long long ull;
typedef unsigned int u32;

// ---------------- scratch (device globals) ----------------
__device__ float g_h1[BB*HID*NPIX];    // h1, later q
__device__ float g_h2[BB*HID*NPIX];    // h2, later y
__device__ float g_enorm[KC];
__device__ int   g_idx[NTOK];
__device__ int   g_cand[NTOK*16];      // 16 candidate codes per token
__device__ u32   g_Bfrag[STILES*2048]; // codebook bf16 frag-major (2MB)
__device__ float g_wT_e1[CIN*9*HID];
__device__ float g_wT_e2[HID*9*HID];
__device__ float g_wT_d1[HID*9*HID];

__device__ __forceinline__ float gelu_exact(float x) {
    return 0.5f * x * (1.0f + erff(x * 0.70710678118654752440f));
}
__device__ __forceinline__ ull pack2(float x, float y) {
    ull r; asm("mov.b64 %0, {%1, %2};" : "=l"(r) : "f"(x), "f"(y)); return r;
}
__device__ __forceinline__ void unpack2(ull v, float& x, float& y) {
    asm("mov.b64 {%0, %1}, %2;" : "=f"(x), "=f"(y) : "l"(v));
}
__device__ __forceinline__ ull ffma2(ull a, ull b, ull c) {
    ull d; asm("fma.rn.f32x2 %0, %1, %2, %3;" : "=l"(d) : "l"(a), "l"(b), "l"(c)); return d;
}
__device__ __forceinline__ u32 pkbf(float lo, float hi) {
    __nv_bfloat162 v = __floats2bfloat162_rn(lo, hi);
    return *reinterpret_cast<u32*>(&v);
}
__device__ __forceinline__ void mma_bf16(float& d0, float& d1, float& d2, float& d3,
                                         u32 a0, u32 a1, u32 a2, u32 a3, u32 b0, u32 b1) {
    asm volatile(
        "mma.sync.aligned.m16n8k16.row.col.f32.bf16.bf16.f32 "
        "{%0,%1,%2,%3},{%4,%5,%6,%7},{%8,%9},{%0,%1,%2,%3};"
        : "+f"(d0), "+f"(d1), "+f"(d2), "+f"(d3)
        : "r"(a0), "r"(a1), "r"(a2), "r"(a3), "r"(b0), "r"(b1));
}
__device__ __forceinline__ unsigned fmono(float x) {
    unsigned u = __float_as_uint(x);
    return (u & 0x80000000u) ? ~u : (u | 0x80000000u);
}
__device__ __forceinline__ void ins4(ull& k0, ull& k1, ull& k2, ull& k3, ull key) {
    if (key < k3) {
        if (key < k1) {
            if (key < k0) { k3 = k2; k2 = k1; k1 = k0; k0 = key; }
            else          { k3 = k2; k2 = k1; k1 = key; }
        } else {
            if (key < k2) { k3 = k2; k2 = key; }
            else          { k3 = key; }
        }
    }
}

// ---------------- prep: code norms (fp32) ----------------
__global__ void enorm_kernel(const float* __restrict__ e) {
    int warp = (blockIdx.x * blockDim.x + threadIdx.x) >> 5;
    int lane = threadIdx.x & 31;
    if (warp >= KC) return;
    float4 v = *(const float4*)(e + (size_t)warp * HID + lane * 4);
    float s = v.x*v.x + v.y*v.y + v.z*v.z + v.w*v.w;
    #pragma unroll
    for (int o = 16; o; o >>= 1) s += __shfl_xor_sync(0xffffffffu, s, o);
    if (lane == 0) g_enorm[warp] = s;
}

// ---------------- prep: codebook -> bf16 fragment-major ----------------
// layout u32 [stile][kstep(8)][lane(32)][ntile(4)][reg(2)]
__global__ void bfrag_kernel(const float* __restrict__ e) {
    int u = blockIdx.x * 256 + threadIdx.x;
    if (u >= STILES * 2048) return;
    int r    = u & 1;
    int nt   = (u >> 1) & 3;
    int lane = (u >> 3) & 31;
    int ks   = (u >> 8) & 7;
    int st   = u >> 11;
    int g = lane >> 2, t = lane & 3;
    int n = st * 32 + nt * 8 + g;
    int k = ks * 16 + 2 * t + 8 * r;
    g_Bfrag[u] = pkbf(e[(size_t)n * HID + k], e[(size_t)n * HID + k + 1]);
}

__global__ void transpose_w_kernel(const float* __restrict__ w, float* __restrict__ wT, int cin) {
    int e = blockIdx.x * 256 + threadIdx.x;
    int total = cin * 9 * HID;
    if (e >= total) return;
    int row = e >> 7, oc = e & 127;
    wT[e] = w[(size_t)oc * cin * 9 + row];
}

// ---------------- conv 3x3 SAME + GELU (f32x2) ----------------
__global__ void conv3x3_f2_kernel(const float* __restrict__ in, const float* __restrict__ wT,
                                  const float* __restrict__ bias, float* __restrict__ out, int cin) {
    __shared__ float in_s[16 * 324];
    __shared__ float w_s[144 * 32];
    int tile = blockIdx.x, ocb = blockIdx.y, b = blockIdx.z;
    int ty0 = (tile >> 2) * 16, tx0 = (tile & 3) * 16;
    int tid = threadIdx.x;
    int px = tid & 15, py = tid >> 4;

    ull acc[16];
    #pragma unroll
    for (int o = 0; o < 16; o++) acc[o] = 0ull;

    int chunks = cin >> 4;
    for (int cc = 0; cc < chunks; cc++) {
        int ci0 = cc * 16;
        __syncthreads();
        for (int e = tid; e < 16 * 324; e += 256) {
            int ci = e / 324, r = e % 324;
            int iy = r / 18, ix = r % 18;
            int gy = ty0 + iy - 1, gx = tx0 + ix - 1;
            float v = 0.f;
            if ((unsigned)gy < 64u && (unsigned)gx < 64u)
                v = in[((size_t)b * cin + ci0 + ci) * NPIX + gy * HW + gx];
            in_s[e] = v;
        }
        for (int e = tid; e < 144 * 32; e += 256) {
            int r = e >> 5, o = e & 31;
            w_s[e] = wT[(size_t)(ci0 * 9 + r) * HID + ocb * 32 + o];
        }
        __syncthreads();

        for (int ci = 0; ci < 16; ci++) {
            #pragma unroll
            for (int ky = 0; ky < 3; ky++) {
                #pragma unroll
                for (int kx = 0; kx < 3; kx++) {
                    float v = in_s[ci * 324 + (py + ky) * 18 + (px + kx)];
                    ull vd = pack2(v, v);
                    const ulonglong2* wp = (const ulonglong2*)(w_s + (ci * 9 + ky * 3 + kx) * 32);
                    #pragma unroll
                    for (int q = 0; q < 8; q++) {
                        ulonglong2 wv = wp[q];
                        acc[2*q]   = ffma2(wv.x, vd, acc[2*q]);
                        acc[2*q+1] = ffma2(wv.y, vd, acc[2*q+1]);
                    }
                }
            }
        }
    }

    int gy = ty0 + py, gx = tx0 + px;
    #pragma unroll
    for (int o = 0; o < 16; o++) {
        float f0, f1;
        unpack2(acc[o], f0, f1);
        int oc = ocb * 32 + 2 * o;
        out[((size_t)(b * HID + oc)) * NPIX + gy * HW + gx]     = gelu_exact(f0 + bias[oc]);
        out[((size_t)(b * HID + oc + 1)) * NPIX + gy * HW + gx] = gelu_exact(f1 + bias[oc + 1]);
    }
}

// ---------------- VQ pass 1: bf16 mma.sync approx distances + top-4/lane ----------------
// CTA: 256 threads = 8 warps; 128 tokens (warp w owns tokens w*16..w*16+15).
// Loops 256 stiles of 32 codes. A-frags in registers, B double-buffered in smem.
__global__ void __launch_bounds__(256, 2) vq_pass1_kernel() {
    __shared__ u32  smB[2][2048];     // 8KB per buffer, frag-major
    __shared__ float ensS[2][32];

    int tid = threadIdx.x, w = tid >> 5, lane = tid & 31;
    int g = lane >> 2, t = lane & 3;
    int n0 = blockIdx.x * 128;
    int b = n0 / NPIX, hw0 = n0 % NPIX;

    // build A fragments (bf16) for this warp's 16 tokens, all 128 dims
    const float* fbase = g_h2 + (size_t)b * HID * NPIX + hw0 + w * 16;
    u32 A[8][4];
    #pragma unroll
    for (int ks = 0; ks < 8; ks++) {
        #pragma unroll
        for (int r = 0; r < 4; r++) {
            int row = (r & 1) ? g + 8 : g;
            int k0 = ks * 16 + 2 * t + ((r >> 1) ? 8 : 0);
            A[ks][r] = pkbf(fbase[(size_t)k0 * NPIX + row],
                            fbase[(size_t)(k0 + 1) * NPIX + row]);
        }
    }

    // preload stile 0
    {
        const uint4* src = (const uint4*)g_Bfrag;
        ((uint4*)smB[0])[tid]       = src[tid];
        ((uint4*)smB[0])[tid + 256] = src[tid + 256];
        if (tid < 32) ensS[0][tid] = g_enorm[tid];
    }
    __syncthreads();

    // top-4 keys: token A (row g) and token B (row g+8)
    ull a0k = ~0ull, a1k = ~0ull, a2k = ~0ull, a3k = ~0ull;
    ull b0k = ~0ull, b1k = ~0ull, b2k = ~0ull, b3k = ~0ull;

    for (int s = 0; s < STILES; s++) {
        int cur = s & 1, nxt = cur ^ 1;
        uint4 p0, p1; float pe = 0.f;
        if (s + 1 < STILES) {
            const uint4* src = (const uint4*)(g_Bfrag + (size_t)(s + 1) * 2048);
            p0 = src[tid]; p1 = src[tid + 256];
            if (tid < 32) pe = g_enorm[(s + 1) * 32 + tid];
        }

        float d[4][4];
        #pragma unroll
        for (int i = 0; i < 4; i++)
            #pragma unroll
            for (int j = 0; j < 4; j++) d[i][j] = 0.f;

        #pragma unroll
        for (int ks = 0; ks < 8; ks++) {
            uint4 bA = *(const uint4*)&smB[cur][ks * 256 + lane * 8];
            uint4 bB = *(const uint4*)&smB[cur][ks * 256 + lane * 8 + 4];
            mma_bf16(d[0][0], d[0][1], d[0][2], d[0][3], A[ks][0], A[ks][1], A[ks][2], A[ks][3], bA.x, bA.y);
            mma_bf16(d[1][0], d[1][1], d[1][2], d[1][3], A[ks][0], A[ks][1], A[ks][2], A[ks][3], bA.z, bA.w);
            mma_bf16(d[2][0], d[2][1], d[2][2], d[2][3], A[ks][0], A[ks][1], A[ks][2], A[ks][3], bB.x, bB.y);
            mma_bf16(d[3][0], d[3][1], d[3][2], d[3][3], A[ks][0], A[ks][1], A[ks][2], A[ks][3], bB.z, bB.w);
        }

        int cbase = s * 32;
        #pragma unroll
        for (int nt = 0; nt < 4; nt++) {
            int col0 = nt * 8 + 2 * t, col1 = col0 + 1;
            float e0 = ensS[cur][col0], e1 = ensS[cur][col1];
            unsigned i0 = (unsigned)(cbase + col0), i1 = (unsigned)(cbase + col1);
            ull kA0 = ((ull)fmono(e0 - 2.0f * d[nt][0]) << 32) | i0;
            ull kA1 = ((ull)fmono(e1 - 2.0f * d[nt][1]) << 32) | i1;
            ull kB0 = ((ull)fmono(e0 - 2.0f * d[nt][2]) << 32) | i0;
            ull kB1 = ((ull)fmono(e1 - 2.0f * d[nt][3]) << 32) | i1;
            ins4(a0k, a1k, a2k, a3k, kA0);
            ins4(a0k, a1k, a2k, a3k, kA1);
            ins4(b0k, b1k, b2k, b3k, kB0);
            ins4(b0k, b1k, b2k, b3k, kB1);
        }

        __syncthreads();
        if (s + 1 < STILES) {
            ((uint4*)smB[nxt])[tid]       = p0;
            ((uint4*)smB[nxt])[tid + 256] = p1;
            if (tid < 32) ensS[nxt][tid] = pe;
        }
        __syncthreads();
    }

    int tokA = n0 + w * 16 + g;
    int tokB = tokA + 8;
    g_cand[tokA * 16 + t * 4 + 0] = (int)(a0k & 0xFFFFFFFFu);
    g_cand[tokA * 16 + t * 4 + 1] = (int)(a1k & 0xFFFFFFFFu);
    g_cand[tokA * 16 + t * 4 + 2] = (int)(a2k & 0xFFFFFFFFu);
    g_cand[tokA * 16 + t * 4 + 3] = (int)(a3k & 0xFFFFFFFFu);
    g_cand[tokB * 16 + t * 4 + 0] = (int)(b0k & 0xFFFFFFFFu);
    g_cand[tokB * 16 + t * 4 + 1] = (int)(b1k & 0xFFFFFFFFu);
    g_cand[tokB * 16 + t * 4 + 2] = (int)(b2k & 0xFFFFFFFFu);
    g_cand[tokB * 16 + t * 4 + 3] = (int)(b3k & 0xFFFFFFFFu);
}

// ---------------- VQ pass 2: exact fp32 rescore of 16 candidates/token ----------------
__global__ void vq_rescore_kernel(const float* __restrict__ embed) {
    int warp = threadIdx.x >> 5, lane = threadIdx.x & 31;
    int tok = blockIdx.x * 8 + warp;
    int b = tok / NPIX, hw = tok % NPIX;
    const float* fb = g_h2 + (size_t)b * HID * NPIX + hw;
    float f0 = fb[(size_t)(lane * 4 + 0) * NPIX];
    float f1 = fb[(size_t)(lane * 4 + 1) * NPIX];
    float f2 = fb[(size_t)(lane * 4 + 2) * NPIX];
    float f3 = fb[(size_t)(lane * 4 + 3) * NPIX];

    ull best = ~0ull;
    #pragma unroll 1
    for (int j = 0; j < 16; j++) {
        int c = g_cand[tok * 16 + j];
        float4 e = *(const float4*)(embed + (size_t)c * HID + lane * 4);
        float p = f0 * e.x + f1 * e.y + f2 * e.z + f3 * e.w;
        #pragma unroll
        for (int o = 16; o; o >>= 1) p += __shfl_xor_sync(0xffffffffu, p, o);
        float d2 = g_enorm[c] - 2.0f * p;
        ull key = ((ull)fmono(d2) << 32) | (unsigned)c;
        if (key < best) best = key;
    }
    if (lane == 0) g_idx[tok] = (int)(best & 0xFFFFFFFFu);
}

// ---------------- gather codebook -> NCHW q ----------------
__global__ void gather_kernel(const float* __restrict__ embed) {
    int n = blockIdx.x * 256 + threadIdx.x;
    int id = g_idx[n];
    int b = n / NPIX, hw = n % NPIX;
    float* q = g_h1 + (size_t)b * HID * NPIX + hw;
    const float* er = embed + (size_t)id * HID;
    #pragma unroll 4
    for (int d = 0; d < HID; d += 4) {
        float4 v = *(const float4*)(er + d);
        q[(d + 0) * NPIX] = v.x;
        q[(d + 1) * NPIX] = v.y;
        q[(d + 2) * NPIX] = v.z;
        q[(d + 3) * NPIX] = v.w;
    }
}

// ---------------- conv1x1 128->16 + sigmoid ----------------
__global__ void conv1x1_sigmoid_kernel(const float* __restrict__ y, const float* __restrict__ w,
                                       const float* __restrict__ bias, float* __restrict__ out) {
    __shared__ float w_s[CIN * HID];
    int tid = threadIdx.x;
    for (int e = tid; e < CIN * HID; e += 256) w_s[e] = w[e];
    __syncthreads();

    int b = blockIdx.y;
    int p = blockIdx.x * 256 + tid;
    const float* yb = y + (size_t)b * HID * NPIX + p;
    float acc[CIN];
    #pragma unroll
    for (int c = 0; c < CIN; c++) acc[c] = 0.f;
    #pragma unroll 4
    for (int d = 0; d < HID; d++) {
        float v = yb[d * NPIX];
        #pragma unroll
        for (int c = 0; c < CIN; c++) acc[c] += w_s[c * HID + d] * v;
    }
    #pragma unroll
    for (int c = 0; c < CIN; c++) {
        float s = acc[c] + bias[c];
        out[((size_t)(b * CIN + c)) * NPIX + p] = 1.0f / (1.0f + expf(-s));
    }
}

// ----------------------------------------------------------------
extern "C" void kernel_launch(void* const* d_in, const int* in_sizes, int n_in,
                              void* d_out, int out_size) {
    const float* x     = (const float*)d_in[0];
    const float* ew1   = (const float*)d_in[1];
    const float* eb1   = (const float*)d_in[2];
    const float* ew2   = (const float*)d_in[3];
    const float* eb2   = (const float*)d_in[4];
    const float* embed = (const float*)d_in[5];
    const float* dw1   = (const float*)d_in[6];
    const float* db1   = (const float*)d_in[7];
    const float* dw2   = (const float*)d_in[8];
    const float* db2   = (const float*)d_in[9];
    float* out = (float*)d_out;

    float *p_h1, *p_h2, *p_wT_e1, *p_wT_e2, *p_wT_d1;
    cudaGetSymbolAddress((void**)&p_h1, g_h1);
    cudaGetSymbolAddress((void**)&p_h2, g_h2);
    cudaGetSymbolAddress((void**)&p_wT_e1, g_wT_e1);
    cudaGetSymbolAddress((void**)&p_wT_e2, g_wT_e2);
    cudaGetSymbolAddress((void**)&p_wT_d1, g_wT_d1);

    // prep (independent of activations)
    enorm_kernel<<<KC * 32 / 256, 256>>>(embed);
    bfrag_kernel<<<STILES * 2048 / 256, 256>>>(embed);
    transpose_w_kernel<<<(CIN * 9 * HID + 255) / 256, 256>>>(ew1, p_wT_e1, CIN);
    transpose_w_kernel<<<(HID * 9 * HID + 255) / 256, 256>>>(ew2, p_wT_e2, HID);
    transpose_w_kernel<<<(HID * 9 * HID + 255) / 256, 256>>>(dw1, p_wT_d1, HID);

    // encoder
    conv3x3_f2_kernel<<<dim3(16, 4, BB), 256>>>(x, p_wT_e1, eb1, p_h1, CIN);
    conv3x3_f2_kernel<<<dim3(16, 4, BB), 256>>>(p_h1, p_wT_e2, eb2, p_h2, HID);

    // VQ: bf16 tensor-core prune + exact fp32 rescore
    vq_pass1_kernel<<<NTOK / 128, 256>>>();
    vq_rescore_kernel<<<NTOK / 8, 256>>>(embed);
    gather_kernel<<<NTOK / 256, 256>>>(embed);

    // decoder
    conv3x3_f2_kernel<<<dim3(16, 4, BB), 256>>>(p_h1, p_wT_d1, db1, p_h2, HID);
    conv1x1_sigmoid_kernel<<<dim3(NPIX / 256, BB), 256>>>(p_h2, dw2, db2, out);
}

// round 10
// speedup vs baseline: 2.6812x; 1.2381x over previous
#include <cuda_runtime.h>
#include <cuda_bf16.h>
#include <math.h>
#include <stdint.h>

#define BB   8
#define CIN  16
#define HID  128
#define HW   64
#define NPIX (HW*HW)          // 4096
#define NTOK (BB*NPIX)        // 32768
#define KC   8192             // codebook size
#define STILES 256            // 32-code supertiles

typedef unsigned long long ull;
typedef unsigned int u32;

// ---------------- scratch (device globals) ----------------
__device__ float g_h1[BB*HID*NPIX];    // h1, later q
__device__ float g_h2[BB*HID*NPIX];    // h2, later y
__device__ float g_enorm[KC];
__device__ int   g_idx[NTOK];
__device__ int   g_cand[NTOK*16];      // 16 candidate codes per token
__device__ u32   g_Bfrag[STILES*2048]; // codebook bf16 frag-major (2MB)
__device__ float g_wT_e1[CIN*9*HID];
__device__ float g_wT_e2[HID*9*HID];
__device__ float g_wT_d1[HID*9*HID];

__device__ __forceinline__ float gelu_exact(float x) {
    return 0.5f * x * (1.0f + erff(x * 0.70710678118654752440f));
}
__device__ __forceinline__ ull pack2(float x, float y) {
    ull r; asm("mov.b64 %0, {%1, %2};" : "=l"(r) : "f"(x), "f"(y)); return r;
}
__device__ __forceinline__ void unpack2(ull v, float& x, float& y) {
    asm("mov.b64 {%0, %1}, %2;" : "=f"(x), "=f"(y) : "l"(v));
}
__device__ __forceinline__ ull ffma2(ull a, ull b, ull c) {
    ull d; asm("fma.rn.f32x2 %0, %1, %2, %3;" : "=l"(d) : "l"(a), "l"(b), "l"(c)); return d;
}
__device__ __forceinline__ u32 pkbf(float lo, float hi) {
    __nv_bfloat162 v = __floats2bfloat162_rn(lo, hi);
    return *reinterpret_cast<u32*>(&v);
}
__device__ __forceinline__ void mma_bf16(float& d0, float& d1, float& d2, float& d3,
                                         u32 a0, u32 a1, u32 a2, u32 a3, u32 b0, u32 b1) {
    asm volatile(
        "mma.sync.aligned.m16n8k16.row.col.f32.bf16.bf16.f32 "
        "{%0,%1,%2,%3},{%4,%5,%6,%7},{%8,%9},{%0,%1,%2,%3};"
        : "+f"(d0), "+f"(d1), "+f"(d2), "+f"(d3)
        : "r"(a0), "r"(a1), "r"(a2), "r"(a3), "r"(b0), "r"(b1));
}
__device__ __forceinline__ unsigned fmono(float x) {
    unsigned u = __float_as_uint(x);
    return (u & 0x80000000u) ? ~u : (u | 0x80000000u);
}
__device__ __forceinline__ float inv_fmono(unsigned h) {
    unsigned u = (h & 0x80000000u) ? (h & 0x7FFFFFFFu) : ~h;
    return __uint_as_float(u);
}
__device__ __forceinline__ void ins4(ull& k0, ull& k1, ull& k2, ull& k3, ull key) {
    if (key < k3) {
        if (key < k1) {
            if (key < k0) { k3 = k2; k2 = k1; k1 = k0; k0 = key; }
            else          { k3 = k2; k2 = k1; k1 = key; }
        } else {
            if (key < k2) { k3 = k2; k2 = key; }
            else          { k3 = key; }
        }
    }
}

// ---------------- prep: code norms (fp32) ----------------
__global__ void enorm_kernel(const float* __restrict__ e) {
    int warp = (blockIdx.x * blockDim.x + threadIdx.x) >> 5;
    int lane = threadIdx.x & 31;
    if (warp >= KC) return;
    float4 v = *(const float4*)(e + (size_t)warp * HID + lane * 4);
    float s = v.x*v.x + v.y*v.y + v.z*v.z + v.w*v.w;
    #pragma unroll
    for (int o = 16; o; o >>= 1) s += __shfl_xor_sync(0xffffffffu, s, o);
    if (lane == 0) g_enorm[warp] = s;
}

// ---------------- prep: codebook -> bf16 fragment-major ----------------
// layout u32 [stile][kstep(8)][lane(32)][ntile(4)][reg(2)]
__global__ void bfrag_kernel(const float* __restrict__ e) {
    int u = blockIdx.x * 256 + threadIdx.x;
    if (u >= STILES * 2048) return;
    int r    = u & 1;
    int nt   = (u >> 1) & 3;
    int lane = (u >> 3) & 31;
    int ks   = (u >> 8) & 7;
    int st   = u >> 11;
    int g = lane >> 2, t = lane & 3;
    int n = st * 32 + nt * 8 + g;
    int k = ks * 16 + 2 * t + 8 * r;
    g_Bfrag[u] = pkbf(e[(size_t)n * HID + k], e[(size_t)n * HID + k + 1]);
}

__global__ void transpose_w_kernel(const float* __restrict__ w, float* __restrict__ wT, int cin) {
    int e = blockIdx.x * 256 + threadIdx.x;
    int total = cin * 9 * HID;
    if (e >= total) return;
    int row = e >> 7, oc = e & 127;
    wT[e] = w[(size_t)oc * cin * 9 + row];
}

// ---------------- conv 3x3 SAME + GELU (f32x2, 2 px/thread) ----------------
// block: 256 threads; output tile 16 rows x 32 cols; thread owns rows py and py+8 at col pxc.
// dynamic smem: in_s [16ci][18][34] + w_s [144][32]
#define CONV_INS  (16*612)
#define CONV_SMEM ((CONV_INS + 144*32) * (int)sizeof(float))
__global__ void __launch_bounds__(256, 2) conv3x3_f2_kernel(
        const float* __restrict__ in, const float* __restrict__ wT,
        const float* __restrict__ bias, float* __restrict__ out, int cin) {
    extern __shared__ float dynsm[];
    float* in_s = dynsm;             // 16 x 18 x 34
    float* w_s  = dynsm + CONV_INS;  // 144 x 32

    int tile = blockIdx.x, ocb = blockIdx.y, b = blockIdx.z;
    int ty0 = (tile >> 1) * 16, tx0 = (tile & 1) * 32;
    int tid = threadIdx.x;
    int pxc = tid & 31, py = tid >> 5;   // py 0..7

    ull acc0[16], acc1[16];
    #pragma unroll
    for (int o = 0; o < 16; o++) { acc0[o] = 0ull; acc1[o] = 0ull; }

    int chunks = cin >> 4;
    for (int cc = 0; cc < chunks; cc++) {
        int ci0 = cc * 16;
        __syncthreads();
        for (int e = tid; e < 16 * 612; e += 256) {
            int ci = e / 612, r = e % 612;
            int iy = r / 34, ix = r % 34;
            int gy = ty0 + iy - 1, gx = tx0 + ix - 1;
            float v = 0.f;
            if ((unsigned)gy < 64u && (unsigned)gx < 64u && iy < 18)
                v = in[((size_t)b * cin + ci0 + ci) * NPIX + gy * HW + gx];
            in_s[e] = v;
        }
        for (int e = tid; e < 144 * 32; e += 256) {
            int r = e >> 5, o = e & 31;
            w_s[e] = wT[(size_t)(ci0 * 9 + r) * HID + ocb * 32 + o];
        }
        __syncthreads();

        for (int ci = 0; ci < 16; ci++) {
            #pragma unroll
            for (int ky = 0; ky < 3; ky++) {
                #pragma unroll
                for (int kx = 0; kx < 3; kx++) {
                    float v0 = in_s[ci * 612 + (py + ky) * 34 + pxc + kx];
                    float v1 = in_s[ci * 612 + (py + 8 + ky) * 34 + pxc + kx];
                    ull vd0 = pack2(v0, v0);
                    ull vd1 = pack2(v1, v1);
                    const ulonglong2* wp = (const ulonglong2*)(w_s + (ci * 9 + ky * 3 + kx) * 32);
                    #pragma unroll
                    for (int q = 0; q < 8; q++) {
                        ulonglong2 wv = wp[q];
                        acc0[2*q]   = ffma2(wv.x, vd0, acc0[2*q]);
                        acc0[2*q+1] = ffma2(wv.y, vd0, acc0[2*q+1]);
                        acc1[2*q]   = ffma2(wv.x, vd1, acc1[2*q]);
                        acc1[2*q+1] = ffma2(wv.y, vd1, acc1[2*q+1]);
                    }
                }
            }
        }
    }

    int gx = tx0 + pxc;
    #pragma unroll
    for (int o = 0; o < 16; o++) {
        int oc = ocb * 32 + 2 * o;
        float bia0 = bias[oc], bia1 = bias[oc + 1];
        float f0, f1;
        unpack2(acc0[o], f0, f1);
        int gy0 = ty0 + py;
        out[((size_t)(b * HID + oc)) * NPIX + gy0 * HW + gx]     = gelu_exact(f0 + bia0);
        out[((size_t)(b * HID + oc + 1)) * NPIX + gy0 * HW + gx] = gelu_exact(f1 + bia1);
        unpack2(acc1[o], f0, f1);
        int gy1 = ty0 + py + 8;
        out[((size_t)(b * HID + oc)) * NPIX + gy1 * HW + gx]     = gelu_exact(f0 + bia0);
        out[((size_t)(b * HID + oc + 1)) * NPIX + gy1 * HW + gx] = gelu_exact(f1 + bia1);
    }
}

// ---------------- VQ pass 1: bf16 mma.sync approx distances + top-4/lane ----------------
__global__ void __launch_bounds__(256, 2) vq_pass1_kernel() {
    __shared__ u32  smB[2][2048];     // 8KB per buffer, frag-major
    __shared__ float ensS[2][32];

    int tid = threadIdx.x, w = tid >> 5, lane = tid & 31;
    int g = lane >> 2, t = lane & 3;
    int n0 = blockIdx.x * 128;
    int b = n0 / NPIX, hw0 = n0 % NPIX;

    // build A fragments (bf16) for this warp's 16 tokens, all 128 dims
    const float* fbase = g_h2 + (size_t)b * HID * NPIX + hw0 + w * 16;
    u32 A[8][4];
    #pragma unroll
    for (int ks = 0; ks < 8; ks++) {
        #pragma unroll
        for (int r = 0; r < 4; r++) {
            int row = (r & 1) ? g + 8 : g;
            int k0 = ks * 16 + 2 * t + ((r >> 1) ? 8 : 0);
            A[ks][r] = pkbf(fbase[(size_t)k0 * NPIX + row],
                            fbase[(size_t)(k0 + 1) * NPIX + row]);
        }
    }

    // preload stile 0
    {
        const uint4* src = (const uint4*)g_Bfrag;
        ((uint4*)smB[0])[tid]       = src[tid];
        ((uint4*)smB[0])[tid + 256] = src[tid + 256];
        if (tid < 32) ensS[0][tid] = g_enorm[tid];
    }
    __syncthreads();

    // top-4 keys + fp32 thresholds for tokens A (row g) and B (row g+8)
    ull a0k = ~0ull, a1k = ~0ull, a2k = ~0ull, a3k = ~0ull;
    ull b0k = ~0ull, b1k = ~0ull, b2k = ~0ull, b3k = ~0ull;
    float thrA = __uint_as_float(0x7f800000u);
    float thrB = __uint_as_float(0x7f800000u);

    for (int s = 0; s < STILES; s++) {
        int cur = s & 1, nxt = cur ^ 1;
        uint4 p0, p1; float pe = 0.f;
        if (s + 1 < STILES) {
            const uint4* src = (const uint4*)(g_Bfrag + (size_t)(s + 1) * 2048);
            p0 = src[tid]; p1 = src[tid + 256];
            if (tid < 32) pe = g_enorm[(s + 1) * 32 + tid];
        }

        float d[4][4];
        #pragma unroll
        for (int i = 0; i < 4; i++)
            #pragma unroll
            for (int j = 0; j < 4; j++) d[i][j] = 0.f;

        #pragma unroll
        for (int ks = 0; ks < 8; ks++) {
            uint4 bA = *(const uint4*)&smB[cur][ks * 256 + lane * 8];
            uint4 bB = *(const uint4*)&smB[cur][ks * 256 + lane * 8 + 4];
            mma_bf16(d[0][0], d[0][1], d[0][2], d[0][3], A[ks][0], A[ks][1], A[ks][2], A[ks][3], bA.x, bA.y);
            mma_bf16(d[1][0], d[1][1], d[1][2], d[1][3], A[ks][0], A[ks][1], A[ks][2], A[ks][3], bA.z, bA.w);
            mma_bf16(d[2][0], d[2][1], d[2][2], d[2][3], A[ks][0], A[ks][1], A[ks][2], A[ks][3], bB.x, bB.y);
            mma_bf16(d[3][0], d[3][1], d[3][2], d[3][3], A[ks][0], A[ks][1], A[ks][2], A[ks][3], bB.z, bB.w);
        }

        int cbase = s * 32;
        #pragma unroll
        for (int nt = 0; nt < 4; nt++) {
            int col0 = nt * 8 + 2 * t, col1 = col0 + 1;
            float e0 = ensS[cur][col0], e1 = ensS[cur][col1];
            unsigned i0 = (unsigned)(cbase + col0), i1 = (unsigned)(cbase + col1);
            float dA0 = e0 - 2.0f * d[nt][0];
            float dA1 = e1 - 2.0f * d[nt][1];
            float dB0 = e0 - 2.0f * d[nt][2];
            float dB1 = e1 - 2.0f * d[nt][3];
            // !(x >= thr) is true when thr is the NaN sentinel -> fills top-4 first
            if (!(dA0 >= thrA)) {
                ins4(a0k, a1k, a2k, a3k, ((ull)fmono(dA0) << 32) | i0);
                thrA = inv_fmono((unsigned)(a3k >> 32));
            }
            if (!(dA1 >= thrA)) {
                ins4(a0k, a1k, a2k, a3k, ((ull)fmono(dA1) << 32) | i1);
                thrA = inv_fmono((unsigned)(a3k >> 32));
            }
            if (!(dB0 >= thrB)) {
                ins4(b0k, b1k, b2k, b3k, ((ull)fmono(dB0) << 32) | i0);
                thrB = inv_fmono((unsigned)(b3k >> 32));
            }
            if (!(dB1 >= thrB)) {
                ins4(b0k, b1k, b2k, b3k, ((ull)fmono(dB1) << 32) | i1);
                thrB = inv_fmono((unsigned)(b3k >> 32));
            }
        }

        // store prefetched tile into the OTHER buffer (no conflict with reads of cur),
        // single barrier per stile.
        if (s + 1 < STILES) {
            ((uint4*)smB[nxt])[tid]       = p0;
            ((uint4*)smB[nxt])[tid + 256] = p1;
            if (tid < 32) ensS[nxt][tid] = pe;
        }
        __syncthreads();
    }

    int tokA = n0 + w * 16 + g;
    int tokB = tokA + 8;
    g_cand[tokA * 16 + t * 4 + 0] = (int)(a0k & 0xFFFFFFFFu);
    g_cand[tokA * 16 + t * 4 + 1] = (int)(a1k & 0xFFFFFFFFu);
    g_cand[tokA * 16 + t * 4 + 2] = (int)(a2k & 0xFFFFFFFFu);
    g_cand[tokA * 16 + t * 4 + 3] = (int)(a3k & 0xFFFFFFFFu);
    g_cand[tokB * 16 + t * 4 + 0] = (int)(b0k & 0xFFFFFFFFu);
    g_cand[tokB * 16 + t * 4 + 1] = (int)(b1k & 0xFFFFFFFFu);
    g_cand[tokB * 16 + t * 4 + 2] = (int)(b2k & 0xFFFFFFFFu);
    g_cand[tokB * 16 + t * 4 + 3] = (int)(b3k & 0xFFFFFFFFu);
}

// ---------------- VQ pass 2: exact fp32 rescore of 16 candidates/token ----------------
__global__ void vq_rescore_kernel(const float* __restrict__ embed) {
    int warp = threadIdx.x >> 5, lane = threadIdx.x & 31;
    int tok = blockIdx.x * 8 + warp;
    int b = tok / NPIX, hw = tok % NPIX;
    const float* fb = g_h2 + (size_t)b * HID * NPIX + hw;
    float f0 = fb[(size_t)(lane * 4 + 0) * NPIX];
    float f1 = fb[(size_t)(lane * 4 + 1) * NPIX];
    float f2 = fb[(size_t)(lane * 4 + 2) * NPIX];
    float f3 = fb[(size_t)(lane * 4 + 3) * NPIX];

    ull best = ~0ull;
    #pragma unroll 1
    for (int j = 0; j < 16; j++) {
        int c = g_cand[tok * 16 + j];
        float4 e = *(const float4*)(embed + (size_t)c * HID + lane * 4);
        float p = f0 * e.x + f1 * e.y + f2 * e.z + f3 * e.w;
        #pragma unroll
        for (int o = 16; o; o >>= 1) p += __shfl_xor_sync(0xffffffffu, p, o);
        float d2 = g_enorm[c] - 2.0f * p;
        ull key = ((ull)fmono(d2) << 32) | (unsigned)c;
        if (key < best) best = key;
    }
    if (lane == 0) g_idx[tok] = (int)(best & 0xFFFFFFFFu);
}

// ---------------- gather codebook -> NCHW q ----------------
__global__ void gather_kernel(const float* __restrict__ embed) {
    int n = blockIdx.x * 256 + threadIdx.x;
    int id = g_idx[n];
    int b = n / NPIX, hw = n % NPIX;
    float* q = g_h1 + (size_t)b * HID * NPIX + hw;
    const float* er = embed + (size_t)id * HID;
    #pragma unroll 4
    for (int d = 0; d < HID; d += 4) {
        float4 v = *(const float4*)(er + d);
        q[(d + 0) * NPIX] = v.x;
        q[(d + 1) * NPIX] = v.y;
        q[(d + 2) * NPIX] = v.z;
        q[(d + 3) * NPIX] = v.w;
    }
}

// ---------------- conv1x1 128->16 + sigmoid (f32x2) ----------------
__global__ void conv1x1_sigmoid_kernel(const float* __restrict__ y, const float* __restrict__ w,
                                       const float* __restrict__ bias, float* __restrict__ out) {
    __shared__ ull w_s2[HID * 8];   // [d][c2] : pair of oc (2*c2, 2*c2+1)
    int tid = threadIdx.x;
    for (int e = tid; e < HID * 8; e += 256) {
        int d = e >> 3, c2 = e & 7;
        w_s2[e] = pack2(w[(size_t)(2 * c2) * HID + d], w[(size_t)(2 * c2 + 1) * HID + d]);
    }
    __syncthreads();

    int b = blockIdx.y;
    int p = blockIdx.x * 256 + tid;
    const float* yb = y + (size_t)b * HID * NPIX + p;
    ull acc[8];
    #pragma unroll
    for (int c = 0; c < 8; c++) acc[c] = 0ull;
    #pragma unroll 4
    for (int d = 0; d < HID; d++) {
        float v = yb[(size_t)d * NPIX];
        ull vd = pack2(v, v);
        const ulonglong2* wp = (const ulonglong2*)(w_s2 + d * 8);
        #pragma unroll
        for (int q = 0; q < 4; q++) {
            ulonglong2 wv = wp[q];
            acc[2*q]   = ffma2(wv.x, vd, acc[2*q]);
            acc[2*q+1] = ffma2(wv.y, vd, acc[2*q+1]);
        }
    }
    #pragma unroll
    for (int c2 = 0; c2 < 8; c2++) {
        float f0, f1;
        unpack2(acc[c2], f0, f1);
        float s0 = f0 + bias[2 * c2];
        float s1 = f1 + bias[2 * c2 + 1];
        out[((size_t)(b * CIN + 2 * c2)) * NPIX + p]     = 1.0f / (1.0f + expf(-s0));
        out[((size_t)(b * CIN + 2 * c2 + 1)) * NPIX + p] = 1.0f / (1.0f + expf(-s1));
    }
}

// ----------------------------------------------------------------
extern "C" void kernel_launch(void* const* d_in, const int* in_sizes, int n_in,
                              void* d_out, int out_size) {
    const float* x     = (const float*)d_in[0];
    const float* ew1   = (const float*)d_in[1];
    const float* eb1   = (const float*)d_in[2];
    const float* ew2   = (const float*)d_in[3];
    const float* eb2   = (const float*)d_in[4];
    const float* embed = (const float*)d_in[5];
    const float* dw1   = (const float*)d_in[6];
    const float* db1   = (const float*)d_in[7];
    const float* dw2   = (const float*)d_in[8];
    const float* db2   = (const float*)d_in[9];
    float* out = (float*)d_out;

    float *p_h1, *p_h2, *p_wT_e1, *p_wT_e2, *p_wT_d1;
    cudaGetSymbolAddress((void**)&p_h1, g_h1);
    cudaGetSymbolAddress((void**)&p_h2, g_h2);
    cudaGetSymbolAddress((void**)&p_wT_e1, g_wT_e1);
    cudaGetSymbolAddress((void**)&p_wT_e2, g_wT_e2);
    cudaGetSymbolAddress((void**)&p_wT_d1, g_wT_d1);

    cudaFuncSetAttribute(conv3x3_f2_kernel, cudaFuncAttributeMaxDynamicSharedMemorySize, CONV_SMEM);

    // prep (independent of activations)
    enorm_kernel<<<KC * 32 / 256, 256>>>(embed);
    bfrag_kernel<<<STILES * 2048 / 256, 256>>>(embed);
    transpose_w_kernel<<<(CIN * 9 * HID + 255) / 256, 256>>>(ew1, p_wT_e1, CIN);
    transpose_w_kernel<<<(HID * 9 * HID + 255) / 256, 256>>>(ew2, p_wT_e2, HID);
    transpose_w_kernel<<<(HID * 9 * HID + 255) / 256, 256>>>(dw1, p_wT_d1, HID);

    // encoder
    conv3x3_f2_kernel<<<dim3(8, 4, BB), 256, CONV_SMEM>>>(x, p_wT_e1, eb1, p_h1, CIN);
    conv3x3_f2_kernel<<<dim3(8, 4, BB), 256, CONV_SMEM>>>(p_h1, p_wT_e2, eb2, p_h2, HID);

    // VQ: bf16 tensor-core prune + exact fp32 rescore
    vq_pass1_kernel<<<NTOK / 128, 256>>>();
    vq_rescore_kernel<<<NTOK / 8, 256>>>(embed);
    gather_kernel<<<NTOK / 256, 256>>>(embed);

    // decoder
    conv3x3_f2_kernel<<<dim3(8, 4, BB), 256, CONV_SMEM>>>(p_h1, p_wT_d1, db1, p_h2, HID);
    conv1x1_sigmoid_kernel<<<dim3(NPIX / 256, BB), 256>>>(p_h2, dw2, db2, out);
}

// round 12
// speedup vs baseline: 3.3362x; 1.2443x over previous
#include <cuda_runtime.h>
#include <cuda_bf16.h>
#include <math.h>
#include <stdint.h>

#define BB   8
#define CIN  16
#define HID  128
#define HW   64
#define NPIX (HW*HW)          // 4096
#define NTOK (BB*NPIX)        // 32768
#define KC   8192             // codebook size
#define STILES 256            // 32-code supertiles

typedef unsigned long long ull;
typedef unsigned int u32;

// ---------------- scratch (device globals) ----------------
__device__ float g_h1[BB*HID*NPIX];    // h1 (encoder)
__device__ float g_h2[BB*HID*NPIX];    // h2 (encoder out), later y (decoder out)
__device__ float g_enorm[KC];
__device__ int   g_cand[NTOK*16];      // 16 candidate codes per token
__device__ u32   g_Bfrag[STILES*2048]; // codebook bf16 frag-major (2MB)
__device__ float g_wT_e1[CIN*9*HID];
__device__ float g_wT_e2[HID*9*HID];
__device__ __nv_bfloat16 g_qbf[NTOK*HID];          // quantized tokens, px-major bf16
#define DC_PAD 136
__device__ __nv_bfloat16 g_wbf[9*HID*DC_PAD];      // decoder conv weights bf16 [off][oc][ci pad]

__device__ __forceinline__ float gelu_exact(float x) {
    return 0.5f * x * (1.0f + erff(x * 0.70710678118654752440f));
}
__device__ __forceinline__ ull pack2(float x, float y) {
    ull r; asm("mov.b64 %0, {%1, %2};" : "=l"(r) : "f"(x), "f"(y)); return r;
}
__device__ __forceinline__ void unpack2(ull v, float& x, float& y) {
    asm("mov.b64 {%0, %1}, %2;" : "=f"(x), "=f"(y) : "l"(v));
}
__device__ __forceinline__ ull ffma2(ull a, ull b, ull c) {
    ull d; asm("fma.rn.f32x2 %0, %1, %2, %3;" : "=l"(d) : "l"(a), "l"(b), "l"(c)); return d;
}
__device__ __forceinline__ u32 pkbf(float lo, float hi) {
    __nv_bfloat162 v = __floats2bfloat162_rn(lo, hi);
    return *reinterpret_cast<u32*>(&v);
}
__device__ __forceinline__ void mma_bf16(float& d0, float& d1, float& d2, float& d3,
                                         u32 a0, u32 a1, u32 a2, u32 a3, u32 b0, u32 b1) {
    asm volatile(
        "mma.sync.aligned.m16n8k16.row.col.f32.bf16.bf16.f32 "
        "{%0,%1,%2,%3},{%4,%5,%6,%7},{%8,%9},{%0,%1,%2,%3};"
        : "+f"(d0), "+f"(d1), "+f"(d2), "+f"(d3)
        : "r"(a0), "r"(a1), "r"(a2), "r"(a3), "r"(b0), "r"(b1));
}
__device__ __forceinline__ unsigned fmono(float x) {
    unsigned u = __float_as_uint(x);
    return (u & 0x80000000u) ? ~u : (u | 0x80000000u);
}
__device__ __forceinline__ float inv_fmono(unsigned h) {
    unsigned u = (h & 0x80000000u) ? (h & 0x7FFFFFFFu) : ~h;
    return __uint_as_float(u);
}
__device__ __forceinline__ void ins4(ull& k0, ull& k1, ull& k2, ull& k3, ull key) {
    if (key < k3) {
        if (key < k1) {
            if (key < k0) { k3 = k2; k2 = k1; k1 = k0; k0 = key; }
            else          { k3 = k2; k2 = k1; k1 = key; }
        } else {
            if (key < k2) { k3 = k2; k2 = key; }
            else          { k3 = key; }
        }
    }
}

// ---------------- prep: code norms (fp32) ----------------
__global__ void enorm_kernel(const float* __restrict__ e) {
    int warp = (blockIdx.x * blockDim.x + threadIdx.x) >> 5;
    int lane = threadIdx.x & 31;
    if (warp >= KC) return;
    float4 v = *(const float4*)(e + (size_t)warp * HID + lane * 4);
    float s = v.x*v.x + v.y*v.y + v.z*v.z + v.w*v.w;
    #pragma unroll
    for (int o = 16; o; o >>= 1) s += __shfl_xor_sync(0xffffffffu, s, o);
    if (lane == 0) g_enorm[warp] = s;
}

// ---------------- prep: codebook -> bf16 fragment-major ----------------
__global__ void bfrag_kernel(const float* __restrict__ e) {
    int u = blockIdx.x * 256 + threadIdx.x;
    if (u >= STILES * 2048) return;
    int r    = u & 1;
    int nt   = (u >> 1) & 3;
    int lane = (u >> 3) & 31;
    int ks   = (u >> 8) & 7;
    int st   = u >> 11;
    int g = lane >> 2, t = lane & 3;
    int n = st * 32 + nt * 8 + g;
    int k = ks * 16 + 2 * t + 8 * r;
    g_Bfrag[u] = pkbf(e[(size_t)n * HID + k], e[(size_t)n * HID + k + 1]);
}

__global__ void transpose_w_kernel(const float* __restrict__ w, float* __restrict__ wT, int cin) {
    int e = blockIdx.x * 256 + threadIdx.x;
    int total = cin * 9 * HID;
    if (e >= total) return;
    int row = e >> 7, oc = e & 127;
    wT[e] = w[(size_t)oc * cin * 9 + row];
}

// ---------------- prep: decoder weights -> bf16 [off][oc][ci pad 136] ----------------
__global__ void wbf_dec_kernel(const float* __restrict__ w) {
    int i = blockIdx.x * 256 + threadIdx.x;
    if (i >= 9 * HID * DC_PAD) return;
    int ci  = i % DC_PAD;
    int oc  = (i / DC_PAD) % HID;
    int off = i / (DC_PAD * HID);
    float v = (ci < HID) ? w[(size_t)(oc * HID + ci) * 9 + off] : 0.f;
    g_wbf[i] = __float2bfloat16(v);
}

// ---------------- encoder conv 3x3 SAME + GELU (f32x2, 2 px/thread) ----------------
#define CONV_INS  (16*612)
#define CONV_SMEM ((CONV_INS + 144*32) * (int)sizeof(float))
__global__ void __launch_bounds__(256, 2) conv3x3_f2_kernel(
        const float* __restrict__ in, const float* __restrict__ wT,
        const float* __restrict__ bias, float* __restrict__ out, int cin) {
    extern __shared__ float dynsm[];
    float* in_s = dynsm;             // 16 x 18 x 34
    float* w_s  = dynsm + CONV_INS;  // 144 x 32

    int tile = blockIdx.x, ocb = blockIdx.y, b = blockIdx.z;
    int ty0 = (tile >> 1) * 16, tx0 = (tile & 1) * 32;
    int tid = threadIdx.x;
    int pxc = tid & 31, py = tid >> 5;   // py 0..7

    ull acc0[16], acc1[16];
    #pragma unroll
    for (int o = 0; o < 16; o++) { acc0[o] = 0ull; acc1[o] = 0ull; }

    int chunks = cin >> 4;
    for (int cc = 0; cc < chunks; cc++) {
        int ci0 = cc * 16;
        __syncthreads();
        for (int e = tid; e < 16 * 612; e += 256) {
            int ci = e / 612, r = e % 612;
            int iy = r / 34, ix = r % 34;
            int gy = ty0 + iy - 1, gx = tx0 + ix - 1;
            float v = 0.f;
            if ((unsigned)gy < 64u && (unsigned)gx < 64u && iy < 18)
                v = in[((size_t)b * cin + ci0 + ci) * NPIX + gy * HW + gx];
            in_s[e] = v;
        }
        for (int e = tid; e < 144 * 32; e += 256) {
            int r = e >> 5, o = e & 31;
            w_s[e] = wT[(size_t)(ci0 * 9 + r) * HID + ocb * 32 + o];
        }
        __syncthreads();

        for (int ci = 0; ci < 16; ci++) {
            #pragma unroll
            for (int ky = 0; ky < 3; ky++) {
                #pragma unroll
                for (int kx = 0; kx < 3; kx++) {
                    float v0 = in_s[ci * 612 + (py + ky) * 34 + pxc + kx];
                    float v1 = in_s[ci * 612 + (py + 8 + ky) * 34 + pxc + kx];
                    ull vd0 = pack2(v0, v0);
                    ull vd1 = pack2(v1, v1);
                    const ulonglong2* wp = (const ulonglong2*)(w_s + (ci * 9 + ky * 3 + kx) * 32);
                    #pragma unroll
                    for (int q = 0; q < 8; q++) {
                        ulonglong2 wv = wp[q];
                        acc0[2*q]   = ffma2(wv.x, vd0, acc0[2*q]);
                        acc0[2*q+1] = ffma2(wv.y, vd0, acc0[2*q+1]);
                        acc1[2*q]   = ffma2(wv.x, vd1, acc1[2*q]);
                        acc1[2*q+1] = ffma2(wv.y, vd1, acc1[2*q+1]);
                    }
                }
            }
        }
    }

    int gx = tx0 + pxc;
    #pragma unroll
    for (int o = 0; o < 16; o++) {
        int oc = ocb * 32 + 2 * o;
        float bia0 = bias[oc], bia1 = bias[oc + 1];
        float f0, f1;
        unpack2(acc0[o], f0, f1);
        int gy0 = ty0 + py;
        out[((size_t)(b * HID + oc)) * NPIX + gy0 * HW + gx]     = gelu_exact(f0 + bia0);
        out[((size_t)(b * HID + oc + 1)) * NPIX + gy0 * HW + gx] = gelu_exact(f1 + bia1);
        unpack2(acc1[o], f0, f1);
        int gy1 = ty0 + py + 8;
        out[((size_t)(b * HID + oc)) * NPIX + gy1 * HW + gx]     = gelu_exact(f0 + bia0);
        out[((size_t)(b * HID + oc + 1)) * NPIX + gy1 * HW + gx] = gelu_exact(f1 + bia1);
    }
}

// ---------------- decoder conv 3x3 SAME + GELU: bf16 mma.sync ----------------
// CTA 256 thr = 8 warps (2 M-groups x 4 N-groups). Out tile 8 rows x 16 cols, all 128 oc.
// A: q_bf px-major tile 10x18 px x 136ci-pad in smem. W: per-offset [128oc][136ci-pad].
#define DC_INS (180*DC_PAD)
#define DC_WS  (HID*DC_PAD)
#define DC_SMEM ((DC_INS + DC_WS) * 2)    // bytes (bf16)
__global__ void __launch_bounds__(256, 2) conv_dec_mma_kernel(
        const float* __restrict__ bias, float* __restrict__ out) {
    extern __shared__ __nv_bfloat16 dsm[];
    __nv_bfloat16* in_s = dsm;            // [10*18 px][136]
    __nv_bfloat16* w_s  = dsm + DC_INS;   // [128 oc][136]

    int tile = blockIdx.x, b = blockIdx.z;
    int ty0 = (tile >> 2) * 8, tx0 = (tile & 3) * 16;
    int tid = threadIdx.x, w = tid >> 5, t = tid & 31;
    int mg = w >> 2, n0 = (w & 3) * 32;

    // load A tile (zero-padded halo), coalesced 16B chunks
    for (int e = tid; e < 180 * 16; e += 256) {
        int px = e >> 4, seg = e & 15;
        int gy = ty0 - 1 + px / 18, gx = tx0 - 1 + px % 18;
        uint4 v = make_uint4(0u, 0u, 0u, 0u);
        if ((unsigned)gy < 64u && (unsigned)gx < 64u)
            v = *(const uint4*)(g_qbf + ((size_t)(b * NPIX + gy * HW + gx)) * HID + seg * 8);
        *(uint4*)&in_s[px * DC_PAD + seg * 8] = v;
    }

    float acc[4][4][4];
    #pragma unroll
    for (int m = 0; m < 4; m++)
        #pragma unroll
        for (int n = 0; n < 4; n++)
            #pragma unroll
            for (int r = 0; r < 4; r++) acc[m][n][r] = 0.f;

    int tq = t & 3, tr = t >> 2;

    for (int off = 0; off < 9; off++) {
        int ky = off / 3, kx = off % 3;
        __syncthreads();
        for (int e = tid; e < DC_WS / 8; e += 256)
            *(uint4*)&w_s[e * 8] = *(const uint4*)(g_wbf + (size_t)off * DC_WS + e * 8);
        __syncthreads();

        #pragma unroll
        for (int ks = 0; ks < 8; ks++) {
            u32 b0[4], b1[4];
            #pragma unroll
            for (int nt = 0; nt < 4; nt++) {
                int base = (n0 + nt * 8 + tr) * DC_PAD + ks * 16 + 2 * tq;
                b0[nt] = *(const u32*)&w_s[base];
                b1[nt] = *(const u32*)&w_s[base + 8];
            }
            #pragma unroll
            for (int mt = 0; mt < 4; mt++) {
                int prow = (mg * 4 + mt + ky) * 18 + kx;
                int abase = (prow + tr) * DC_PAD + ks * 16 + 2 * tq;
                u32 a0 = *(const u32*)&in_s[abase];
                u32 a2 = *(const u32*)&in_s[abase + 8];
                u32 a1 = *(const u32*)&in_s[abase + 8 * DC_PAD];
                u32 a3 = *(const u32*)&in_s[abase + 8 * DC_PAD + 8];
                #pragma unroll
                for (int nt = 0; nt < 4; nt++)
                    mma_bf16(acc[mt][nt][0], acc[mt][nt][1], acc[mt][nt][2], acc[mt][nt][3],
                             a0, a1, a2, a3, b0[nt], b1[nt]);
            }
        }
    }

    // epilogue: bias + gelu, NCHW fp32
    #pragma unroll
    for (int mt = 0; mt < 4; mt++) {
        int gy = ty0 + mg * 4 + mt;
        #pragma unroll
        for (int nt = 0; nt < 4; nt++) {
            int oc = n0 + nt * 8 + 2 * tq;
            float bi0 = bias[oc], bi1 = bias[oc + 1];
            size_t base0 = ((size_t)(b * HID + oc)) * NPIX + gy * HW + tx0;
            size_t base1 = base0 + NPIX;
            out[base0 + tr]     = gelu_exact(acc[mt][nt][0] + bi0);
            out[base1 + tr]     = gelu_exact(acc[mt][nt][1] + bi1);
            out[base0 + tr + 8] = gelu_exact(acc[mt][nt][2] + bi0);
            out[base1 + tr + 8] = gelu_exact(acc[mt][nt][3] + bi1);
        }
    }
}

// ---------------- VQ pass 1: bf16 mma.sync approx distances + top-4/lane ----------------
__global__ void __launch_bounds__(256, 2) vq_pass1_kernel() {
    __shared__ u32  smB[2][2048];
    __shared__ float ensS[2][32];

    int tid = threadIdx.x, w = tid >> 5, lane = tid & 31;
    int g = lane >> 2, t = lane & 3;
    int n0 = blockIdx.x * 128;
    int b = n0 / NPIX, hw0 = n0 % NPIX;

    const float* fbase = g_h2 + (size_t)b * HID * NPIX + hw0 + w * 16;
    u32 A[8][4];
    #pragma unroll
    for (int ks = 0; ks < 8; ks++) {
        #pragma unroll
        for (int r = 0; r < 4; r++) {
            int row = (r & 1) ? g + 8 : g;
            int k0 = ks * 16 + 2 * t + ((r >> 1) ? 8 : 0);
            A[ks][r] = pkbf(fbase[(size_t)k0 * NPIX + row],
                            fbase[(size_t)(k0 + 1) * NPIX + row]);
        }
    }

    {
        const uint4* src = (const uint4*)g_Bfrag;
        ((uint4*)smB[0])[tid]       = src[tid];
        ((uint4*)smB[0])[tid + 256] = src[tid + 256];
        if (tid < 32) ensS[0][tid] = g_enorm[tid];
    }
    __syncthreads();

    ull a0k = ~0ull, a1k = ~0ull, a2k = ~0ull, a3k = ~0ull;
    ull b0k = ~0ull, b1k = ~0ull, b2k = ~0ull, b3k = ~0ull;
    float thrA = __uint_as_float(0x7f800000u);
    float thrB = __uint_as_float(0x7f800000u);

    for (int s = 0; s < STILES; s++) {
        int cur = s & 1, nxt = cur ^ 1;
        uint4 p0, p1; float pe = 0.f;
        if (s + 1 < STILES) {
            const uint4* src = (const uint4*)(g_Bfrag + (size_t)(s + 1) * 2048);
            p0 = src[tid]; p1 = src[tid + 256];
            if (tid < 32) pe = g_enorm[(s + 1) * 32 + tid];
        }

        float d[4][4];
        #pragma unroll
        for (int i = 0; i < 4; i++)
            #pragma unroll
            for (int j = 0; j < 4; j++) d[i][j] = 0.f;

        #pragma unroll
        for (int ks = 0; ks < 8; ks++) {
            uint4 bA = *(const uint4*)&smB[cur][ks * 256 + lane * 8];
            uint4 bB = *(const uint4*)&smB[cur][ks * 256 + lane * 8 + 4];
            mma_bf16(d[0][0], d[0][1], d[0][2], d[0][3], A[ks][0], A[ks][1], A[ks][2], A[ks][3], bA.x, bA.y);
            mma_bf16(d[1][0], d[1][1], d[1][2], d[1][3], A[ks][0], A[ks][1], A[ks][2], A[ks][3], bA.z, bA.w);
            mma_bf16(d[2][0], d[2][1], d[2][2], d[2][3], A[ks][0], A[ks][1], A[ks][2], A[ks][3], bB.x, bB.y);
            mma_bf16(d[3][0], d[3][1], d[3][2], d[3][3], A[ks][0], A[ks][1], A[ks][2], A[ks][3], bB.z, bB.w);
        }

        int cbase = s * 32;
        #pragma unroll
        for (int nt = 0; nt < 4; nt++) {
            int col0 = nt * 8 + 2 * t, col1 = col0 + 1;
            float e0 = ensS[cur][col0], e1 = ensS[cur][col1];
            unsigned i0 = (unsigned)(cbase + col0), i1 = (unsigned)(cbase + col1);
            float dA0 = e0 - 2.0f * d[nt][0];
            float dA1 = e1 - 2.0f * d[nt][1];
            float dB0 = e0 - 2.0f * d[nt][2];
            float dB1 = e1 - 2.0f * d[nt][3];
            if (!(dA0 >= thrA)) {
                ins4(a0k, a1k, a2k, a3k, ((ull)fmono(dA0) << 32) | i0);
                thrA = inv_fmono((unsigned)(a3k >> 32));
            }
            if (!(dA1 >= thrA)) {
                ins4(a0k, a1k, a2k, a3k, ((ull)fmono(dA1) << 32) | i1);
                thrA = inv_fmono((unsigned)(a3k >> 32));
            }
            if (!(dB0 >= thrB)) {
                ins4(b0k, b1k, b2k, b3k, ((ull)fmono(dB0) << 32) | i0);
                thrB = inv_fmono((unsigned)(b3k >> 32));
            }
            if (!(dB1 >= thrB)) {
                ins4(b0k, b1k, b2k, b3k, ((ull)fmono(dB1) << 32) | i1);
                thrB = inv_fmono((unsigned)(b3k >> 32));
            }
        }

        if (s + 1 < STILES) {
            ((uint4*)smB[nxt])[tid]       = p0;
            ((uint4*)smB[nxt])[tid + 256] = p1;
            if (tid < 32) ensS[nxt][tid] = pe;
        }
        __syncthreads();
    }

    int tokA = n0 + w * 16 + g;
    int tokB = tokA + 8;
    g_cand[tokA * 16 + t * 4 + 0] = (int)(a0k & 0xFFFFFFFFu);
    g_cand[tokA * 16 + t * 4 + 1] = (int)(a1k & 0xFFFFFFFFu);
    g_cand[tokA * 16 + t * 4 + 2] = (int)(a2k & 0xFFFFFFFFu);
    g_cand[tokA * 16 + t * 4 + 3] = (int)(a3k & 0xFFFFFFFFu);
    g_cand[tokB * 16 + t * 4 + 0] = (int)(b0k & 0xFFFFFFFFu);
    g_cand[tokB * 16 + t * 4 + 1] = (int)(b1k & 0xFFFFFFFFu);
    g_cand[tokB * 16 + t * 4 + 2] = (int)(b2k & 0xFFFFFFFFu);
    g_cand[tokB * 16 + t * 4 + 3] = (int)(b3k & 0xFFFFFFFFu);
}

// ---------------- VQ pass 2: exact fp32 rescore + fused gather (bf16 q, px-major) ----------------
__global__ void vq_rescore_kernel(const float* __restrict__ embed) {
    int warp = threadIdx.x >> 5, lane = threadIdx.x & 31;
    int tok = blockIdx.x * 8 + warp;
    int b = tok / NPIX, hw = tok % NPIX;
    const float* fb = g_h2 + (size_t)b * HID * NPIX + hw;
    float f0 = fb[(size_t)(lane * 4 + 0) * NPIX];
    float f1 = fb[(size_t)(lane * 4 + 1) * NPIX];
    float f2 = fb[(size_t)(lane * 4 + 2) * NPIX];
    float f3 = fb[(size_t)(lane * 4 + 3) * NPIX];

    ull best = ~0ull;
    #pragma unroll 1
    for (int j = 0; j < 16; j++) {
        int c = g_cand[tok * 16 + j];
        float4 e = *(const float4*)(embed + (size_t)c * HID + lane * 4);
        float p = f0 * e.x + f1 * e.y + f2 * e.z + f3 * e.w;
        #pragma unroll
        for (int o = 16; o; o >>= 1) p += __shfl_xor_sync(0xffffffffu, p, o);
        float d2 = g_enorm[c] - 2.0f * p;
        ull key = ((ull)fmono(d2) << 32) | (unsigned)c;
        if (key < best) best = key;
    }
    // all lanes agree on best; gather codeword -> bf16 px-major q
    unsigned bidx = (unsigned)(best & 0xFFFFFFFFu);
    float4 e = *(const float4*)(embed + (size_t)bidx * HID + lane * 4);
    ull pk = ((ull)pkbf(e.z, e.w) << 32) | (ull)pkbf(e.x, e.y);
    *(ull*)(g_qbf + (size_t)tok * HID + lane * 4) = pk;
}

// ---------------- conv1x1 128->16 + sigmoid (f32x2) ----------------
__global__ void conv1x1_sigmoid_kernel(const float* __restrict__ y, const float* __restrict__ w,
                                       const float* __restrict__ bias, float* __restrict__ out) {
    __shared__ ull w_s2[HID * 8];
    int tid = threadIdx.x;
    for (int e = tid; e < HID * 8; e += 256) {
        int d = e >> 3, c2 = e & 7;
        w_s2[e] = pack2(w[(size_t)(2 * c2) * HID + d], w[(size_t)(2 * c2 + 1) * HID + d]);
    }
    __syncthreads();

    int b = blockIdx.y;
    int p = blockIdx.x * 256 + tid;
    const float* yb = y + (size_t)b * HID * NPIX + p;
    ull acc[8];
    #pragma unroll
    for (int c = 0; c < 8; c++) acc[c] = 0ull;
    #pragma unroll 4
    for (int d = 0; d < HID; d++) {
        float v = yb[(size_t)d * NPIX];
        ull vd = pack2(v, v);
        const ulonglong2* wp = (const ulonglong2*)(w_s2 + d * 8);
        #pragma unroll
        for (int q = 0; q < 4; q++) {
            ulonglong2 wv = wp[q];
            acc[2*q]   = ffma2(wv.x, vd, acc[2*q]);
            acc[2*q+1] = ffma2(wv.y, vd, acc[2*q+1]);
        }
    }
    #pragma unroll
    for (int c2 = 0; c2 < 8; c2++) {
        float f0, f1;
        unpack2(acc[c2], f0, f1);
        float s0 = f0 + bias[2 * c2];
        float s1 = f1 + bias[2 * c2 + 1];
        out[((size_t)(b * CIN + 2 * c2)) * NPIX + p]     = 1.0f / (1.0f + expf(-s0));
        out[((size_t)(b * CIN + 2 * c2 + 1)) * NPIX + p] = 1.0f / (1.0f + expf(-s1));
    }
}

// ----------------------------------------------------------------
extern "C" void kernel_launch(void* const* d_in, const int* in_sizes, int n_in,
                              void* d_out, int out_size) {
    const float* x     = (const float*)d_in[0];
    const float* ew1   = (const float*)d_in[1];
    const float* eb1   = (const float*)d_in[2];
    const float* ew2   = (const float*)d_in[3];
    const float* eb2   = (const float*)d_in[4];
    const float* embed = (const float*)d_in[5];
    const float* dw1   = (const float*)d_in[6];
    const float* db1   = (const float*)d_in[7];
    const float* dw2   = (const float*)d_in[8];
    const float* db2   = (const float*)d_in[9];
    float* out = (float*)d_out;

    float *p_h1, *p_h2, *p_wT_e1, *p_wT_e2;
    cudaGetSymbolAddress((void**)&p_h1, g_h1);
    cudaGetSymbolAddress((void**)&p_h2, g_h2);
    cudaGetSymbolAddress((void**)&p_wT_e1, g_wT_e1);
    cudaGetSymbolAddress((void**)&p_wT_e2, g_wT_e2);

    cudaFuncSetAttribute(conv3x3_f2_kernel, cudaFuncAttributeMaxDynamicSharedMemorySize, CONV_SMEM);
    cudaFuncSetAttribute(conv_dec_mma_kernel, cudaFuncAttributeMaxDynamicSharedMemorySize, DC_SMEM);

    // prep (independent of activations)
    enorm_kernel<<<KC * 32 / 256, 256>>>(embed);
    bfrag_kernel<<<STILES * 2048 / 256, 256>>>(embed);
    transpose_w_kernel<<<(CIN * 9 * HID + 255) / 256, 256>>>(ew1, p_wT_e1, CIN);
    transpose_w_kernel<<<(HID * 9 * HID + 255) / 256, 256>>>(ew2, p_wT_e2, HID);
    wbf_dec_kernel<<<(9 * HID * DC_PAD + 255) / 256, 256>>>(dw1);

    // encoder (fp32 exact — feeds argmin)
    conv3x3_f2_kernel<<<dim3(8, 4, BB), 256, CONV_SMEM>>>(x, p_wT_e1, eb1, p_h1, CIN);
    conv3x3_f2_kernel<<<dim3(8, 4, BB), 256, CONV_SMEM>>>(p_h1, p_wT_e2, eb2, p_h2, HID);

    // VQ: bf16 tensor-core prune + exact fp32 rescore (+ fused bf16 gather)
    vq_pass1_kernel<<<NTOK / 128, 256>>>();
    vq_rescore_kernel<<<NTOK / 8, 256>>>(embed);

    // decoder: bf16 mma conv + fp32 1x1 sigmoid
    conv_dec_mma_kernel<<<dim3(32, 1, BB), 256, DC_SMEM>>>(db1, p_h2);
    conv1x1_sigmoid_kernel<<<dim3(NPIX / 256, BB), 256>>>(p_h2, dw2, db2, out);
}